// round 4
// baseline (speedup 1.0000x reference)
#include <cuda_runtime.h>
#include <cstdint>

// MergedEmbeddingBag: T=26 tables, R=100000 rows, D=128, B=4096 bags/table, L=20 bag size.
// Pooling: even tables SUM, odd tables MEAN (scale 1/L).
// Inputs: d_in[0] = W [T,R,D] float32, d_in[1] = indices [T,B,L] int32
//   (JAX x64 is disabled, so the reference's "int64" indices materialize as int32).
// Output: [T,B,D] float32.

constexpr int T = 26;
constexpr int R = 100000;
constexpr int D = 128;
constexpr int B = 4096;
constexpr int L = 20;

__global__ __launch_bounds__(256) void merged_embedding_bag_kernel(
    const float* __restrict__ W,
    const int* __restrict__ indices,
    float* __restrict__ out)
{
    const int gwarp = (blockIdx.x * blockDim.x + threadIdx.x) >> 5;
    const int lane  = threadIdx.x & 31;
    if (gwarp >= T * B) return;

    const int t = gwarp / B;
    const int b = gwarp - t * B;

    const int* __restrict__ bag = indices + ((size_t)t * B + b) * L;
    const float* __restrict__ Wt = W + (size_t)t * R * D;

    // Front-load all 20 indices (warp-uniform broadcast loads), then issue
    // 20 independent float4 gathers so the LSU queue has full MLP.
    int idx[L];
#pragma unroll
    for (int j = 0; j < L; j++) idx[j] = bag[j];

    float4 acc = make_float4(0.f, 0.f, 0.f, 0.f);
#pragma unroll
    for (int j = 0; j < L; j++) {
        const float4* p = reinterpret_cast<const float4*>(Wt + (size_t)idx[j] * D) + lane;
        float4 v = __ldg(p);
        acc.x += v.x; acc.y += v.y; acc.z += v.z; acc.w += v.w;
    }

    const float s = (t & 1) ? (1.0f / (float)L) : 1.0f;
    acc.x *= s; acc.y *= s; acc.z *= s; acc.w *= s;

    float4* o = reinterpret_cast<float4*>(out + ((size_t)t * B + b) * D) + lane;
    *o = acc;
}

extern "C" void kernel_launch(void* const* d_in, const int* in_sizes, int n_in,
                              void* d_out, int out_size)
{
    const float* W = (const float*)d_in[0];
    const int* indices = (const int*)d_in[1];
    float* out = (float*)d_out;

    const int total_warps = T * B;               // 106496
    const int threads = 256;                     // 8 warps / block
    const int blocks = (total_warps * 32 + threads - 1) / threads;  // 13312

    merged_embedding_bag_kernel<<<blocks, threads>>>(W, indices, out);
}

// round 5
// speedup vs baseline: 1.0196x; 1.0196x over previous
#include <cuda_runtime.h>
#include <cstdint>

// MergedEmbeddingBag: T=26 tables, R=100000 rows, D=128, B=4096 bags/table, L=20 bag size.
// Pooling: even tables SUM, odd tables MEAN (scale 1/L).
// Inputs: d_in[0] = W [T,R,D] float32, d_in[1] = indices [T,B,L] int32.
// Output: [T,B,D] float32.
//
// R4 analysis: DRAM traffic is already at the compulsory floor (~808 MB).
// This round: raise per-warp MLP (explicit 10-deep load batches, 64-reg budget)
// to lift DRAM busy% from 83% toward 90%.

constexpr int T = 26;
constexpr int R = 100000;
constexpr int D = 128;
constexpr int B = 4096;
constexpr int L = 20;
constexpr int HALF = L / 2;   // 10

__global__ __launch_bounds__(256, 4) void merged_embedding_bag_kernel(
    const float* __restrict__ W,
    const int* __restrict__ indices,
    float* __restrict__ out)
{
    const int gwarp = (blockIdx.x * blockDim.x + threadIdx.x) >> 5;
    const int lane  = threadIdx.x & 31;
    if (gwarp >= T * B) return;

    const int t = gwarp / B;
    const int b = gwarp - t * B;

    const int* __restrict__ bag = indices + ((size_t)t * B + b) * L;
    const float* __restrict__ Wt = W + (size_t)t * R * D;

    float4 acc = make_float4(0.f, 0.f, 0.f, 0.f);

    // ---- batch 1: 10 independent gathers held live in registers ----
    int idx[HALF];
#pragma unroll
    for (int j = 0; j < HALF; j++) idx[j] = __ldg(bag + j);

    float4 v[HALF];
#pragma unroll
    for (int j = 0; j < HALF; j++)
        v[j] = __ldg(reinterpret_cast<const float4*>(Wt + (size_t)idx[j] * D) + lane);
#pragma unroll
    for (int j = 0; j < HALF; j++) {
        acc.x += v[j].x; acc.y += v[j].y; acc.z += v[j].z; acc.w += v[j].w;
    }

    // ---- batch 2 ----
#pragma unroll
    for (int j = 0; j < HALF; j++) idx[j] = __ldg(bag + HALF + j);

#pragma unroll
    for (int j = 0; j < HALF; j++)
        v[j] = __ldg(reinterpret_cast<const float4*>(Wt + (size_t)idx[j] * D) + lane);
#pragma unroll
    for (int j = 0; j < HALF; j++) {
        acc.x += v[j].x; acc.y += v[j].y; acc.z += v[j].z; acc.w += v[j].w;
    }

    const float s = (t & 1) ? (1.0f / (float)L) : 1.0f;
    acc.x *= s; acc.y *= s; acc.z *= s; acc.w *= s;

    // Streaming store: output lines are dead after write; keep them out of L2's
    // weight-row working set.
    float4* o = reinterpret_cast<float4*>(out + ((size_t)t * B + b) * D) + lane;
    __stcs(o, acc);
}

extern "C" void kernel_launch(void* const* d_in, const int* in_sizes, int n_in,
                              void* d_out, int out_size)
{
    const float* W = (const float*)d_in[0];
    const int* indices = (const int*)d_in[1];
    float* out = (float*)d_out;

    const int total_warps = T * B;               // 106496
    const int threads = 256;                     // 8 warps / block
    const int blocks = (total_warps * 32 + threads - 1) / threads;  // 13312

    merged_embedding_bag_kernel<<<blocks, threads>>>(W, indices, out);
}